// round 16
// baseline (speedup 1.0000x reference)
#include <cuda_runtime.h>
#include <cuda_fp16.h>
#include <cstdint>
#include <cstddef>

#define B 32
#define T 512
#define D 500
#define H 10
#define HD 50
#define D3 1500
#define BT (B*T)
#define BTD (BT*D)
#define KW 7
#define KAP 512      // padded activation K pitch (halves)
#define KAPW 256     // words per activation row
#define QKVP 1920    // padded qkv row pitch (halves): 3 * H * 64

// ---------------- scratch (static device arrays; no runtime allocation) ----
__device__ float  g_b0[BTD];
__device__ float  g_b1[BTD];
__device__ float  g_b2[BTD];
__device__ __half g_bt[(size_t)BT * KAP];
__device__ __half g_b1t[(size_t)BT * KAP];
__device__ __half g_b2t[(size_t)BT * KAP];
__device__ __half g_qkv[(size_t)BT * QKVP];
__device__ __half g_wt[2304000];             // padded fp16 weights (permuted)
__device__ float  g_wtr[4 * KW * D];         // transposed dwconv weights [K][D]
__device__ float  g_pe[T * D];               // positional embedding table

#define PWS 256000   // 500*512
#define INS 768000   // 1500*512
#define NW  (4 * PWS + INS + 2 * PWS)        // 2,304,000 weight halves
#define NTR (4 * KW * D)                     // 14,000 transposed dw weights
#define NPE (T * D)                          // 256,000 PE entries
#define NQZ (BT * 30)                        // 491,520 qkv pad zero jobs

// ---------------- helpers ---------------------------------------------------
__device__ __forceinline__ uint32_t smem_u32(const void* p) {
    uint32_t a;
    asm("{ .reg .u64 t; cvta.to.shared.u64 t, %1; cvt.u32.u64 %0, t; }" : "=r"(a) : "l"(p));
    return a;
}
__device__ __forceinline__ uint32_t pack_h2(float lo, float hi) {
    __half2 h = __floats2half2_rn(lo, hi);
    return *(uint32_t*)&h;
}
// fragment-pair permutation within each 8-word block: new[2k]=old k, new[2k+1]=old k+4
__device__ __forceinline__ int pidx(int w) {
    return (w & ~7) | ((w & 3) << 1) | ((w >> 2) & 1);
}

#define MMA_F16(c, a, b) \
    asm volatile("mma.sync.aligned.m16n8k16.row.col.f32.f16.f16.f32 " \
        "{%0,%1,%2,%3}, {%4,%5,%6,%7}, {%8,%9}, {%0,%1,%2,%3};" \
        : "+f"((c)[0]), "+f"((c)[1]), "+f"((c)[2]), "+f"((c)[3]) \
        : "r"((a)[0]), "r"((a)[1]), "r"((a)[2]), "r"((a)[3]), \
          "r"((b)[0]), "r"((b)[1]))

#define CP16(dst, src) \
    asm volatile("cp.async.ca.shared.global [%0], [%1], 16;" :: "r"(dst), "l"(src) : "memory")
#define CP16P(dst, src, p) \
    asm volatile("cp.async.ca.shared.global [%0], [%1], 16, %2;" :: "r"(dst), "l"(src), "r"(p) : "memory")
#define CPCOMMIT() asm volatile("cp.async.commit_group;" ::: "memory")
#define CPWAIT0()  asm volatile("cp.async.wait_group 0;" ::: "memory")
#define CPWAIT1()  asm volatile("cp.async.wait_group 1;" ::: "memory")

// -------- merged prep: weights fp16 pad-convert (PERMUTED) + dwconv
//          transpose + PE table + qkv pad zero -------------------------------
__global__ void prep_all(const float* __restrict__ p0, const float* __restrict__ p1,
                         const float* __restrict__ p2, const float* __restrict__ p3,
                         const float* __restrict__ p4, const float* __restrict__ p5,
                         const float* __restrict__ p6,
                         const float* __restrict__ dw0, const float* __restrict__ dw1,
                         const float* __restrict__ dw2, const float* __restrict__ dw3,
                         __half* __restrict__ wh, float* __restrict__ otr,
                         float* __restrict__ pe, __half* __restrict__ qkv) {
    int i = blockIdx.x * blockDim.x + threadIdx.x;
    if (i < NW) {
        const float* src;
        int idx;
        if      (i < PWS)          { src = p0; idx = i; }
        else if (i < 2 * PWS)      { src = p1; idx = i - PWS; }
        else if (i < 3 * PWS)      { src = p2; idx = i - 2 * PWS; }
        else if (i < 4 * PWS)      { src = p3; idx = i - 3 * PWS; }
        else if (i < 4 * PWS + INS){ src = p4; idx = i - 4 * PWS; }
        else if (i < 5 * PWS + INS){ src = p5; idx = i - 4 * PWS - INS; }
        else                       { src = p6; idx = i - 5 * PWS - INS; }
        int row = idx >> 9, col = idx & 511;
        float v = (col < 500) ? src[row * 500 + col] : 0.f;
        int newcol = (pidx(col >> 1) << 1) | (col & 1);
        wh[(i & ~511) | newcol] = __float2half(v);
        return;
    }
    int i2 = i - NW;
    if (i2 < NTR) {
        int arr = i2 / (KW * D);
        int rem = i2 - arr * (KW * D);
        int j = rem / D;
        int d = rem - j * D;
        const float* src = (arr == 0) ? dw0 : (arr == 1) ? dw1 : (arr == 2) ? dw2 : dw3;
        otr[arr * KW * D + j * D + d] = src[d * KW + j];
        return;
    }
    int i3 = i2 - NTR;
    if (i3 < NPE) {
        int t = i3 / D, d = i3 - t * D;
        float pos = (float)(t + 1);
        int   k   = (d < 250) ? d : (d - 250);
        float ang = pos * expf((float)k * -0.036989318763f);
        pe[i3] = (d < 250) ? sinf(ang) : cosf(ang);
        return;
    }
    int i4 = i3 - NPE;
    if (i4 < NQZ) {
        int row = i4 / 30, slot = i4 - row * 30;
        uint32_t* p = (uint32_t*)(qkv + (size_t)row * QKVP + slot * 64 + 50);
#pragma unroll
        for (int w = 0; w < 7; w++) p[w] = 0u;
    }
}

// ---------------- posemb (float4) -------------------------------------------
__global__ void posemb_kernel(const int* __restrict__ ori,
                              const float* __restrict__ x,
                              const float* __restrict__ tab,
                              float* __restrict__ out) {
    int idx = blockIdx.x * blockDim.x + threadIdx.x;
    if (idx >= BT * 125) return;
    int d4 = idx % 125;
    int bt = idx / 125;
    int t  = bt % T;
    int d  = d4 * 4;
    size_t off = (size_t)bt * D + d;
    float4 xv = *(const float4*)(x + off);
    if (ori[bt] != 0) {
        float4 pv = *(const float4*)(tab + t * D + d);
        xv.x += pv.x; xv.y += pv.y; xv.z += pv.z; xv.w += pv.w;
    }
    *(float4*)(out + off) = xv;
}

// ------- depthwise conv1d: 4 t-outputs per thread, PERMUTED fp16 out -------
__global__ void dwconv4_kernel(const float* __restrict__ x,
                               const float* __restrict__ wT,   // [KW][D]
                               const float* __restrict__ bias,
                               __half* __restrict__ y) {
    int idx = blockIdx.x * blockDim.x + threadIdx.x;
    if (idx >= (BT / 4) * 128) return;
    int d4  = idx & 127;
    int btq = idx >> 7;
    int b   = btq >> 7;          // T/4 = 128
    int t0  = (btq & 127) * 4;
    uint32_t* yw = (uint32_t*)(y + (size_t)(b * T + t0) * KAP);
    int p0 = pidx(d4 * 2), p1 = pidx(d4 * 2 + 1);
    if (d4 >= 125) {
#pragma unroll
        for (int r = 0; r < 4; r++) {
            uint32_t* row = yw + (size_t)r * KAPW;
            row[p0] = 0u; row[p1] = 0u;
        }
        return;
    }
    int d = d4 * 4;
    float4 bv = *(const float4*)(bias + d);
    float acc[4][4];
#pragma unroll
    for (int r = 0; r < 4; r++) {
        acc[r][0] = bv.x; acc[r][1] = bv.y; acc[r][2] = bv.z; acc[r][3] = bv.w;
    }
    float4 w4[KW];
#pragma unroll
    for (int j = 0; j < KW; j++) w4[j] = *(const float4*)(wT + j * D + d);

    const float* xb = x + (size_t)(b * T) * D + d;
#pragma unroll
    for (int s = 0; s < 10; s++) {
        int tt = t0 + s - 3;
        if (tt >= 0 && tt < T) {
            float4 v = *(const float4*)(xb + (size_t)tt * D);
#pragma unroll
            for (int r = 0; r < 4; r++) {
                int j = s - r;
                if (j >= 0 && j < KW) {
                    acc[r][0] = fmaf(w4[j].x, v.x, acc[r][0]);
                    acc[r][1] = fmaf(w4[j].y, v.y, acc[r][1]);
                    acc[r][2] = fmaf(w4[j].z, v.z, acc[r][2]);
                    acc[r][3] = fmaf(w4[j].w, v.w, acc[r][3]);
                }
            }
        }
    }
#pragma unroll
    for (int r = 0; r < 4; r++) {
        uint32_t* row = yw + (size_t)r * KAPW;
        row[p0] = pack_h2(acc[r][0], acc[r][1]);
        row[p1] = pack_h2(acc[r][2], acc[r][3]);
    }
}

// =================== pipelined fp16 warp-mma GEMM (512 threads) =============
// 16 warps x (32x32) tiles; same 2-stage cp.async pipeline, permuted LDS.64.
#define GBM 128
#define GBN 128
#define AP 40
#define GBUF ((GBM + GBN) * AP)
#define GSM_BYTES (2 * GBUF * 4)
#define KTC 8   // 512 / 64

__global__ __launch_bounds__(512, 2)
void gemm_pipe(const __half* __restrict__ A, const __half* __restrict__ W,
               const float* __restrict__ bias, const float* __restrict__ res,
               float* __restrict__ C, __half* __restrict__ Ct,
               int N, int mode) {
    extern __shared__ uint32_t sm[];

    int tid  = threadIdx.x;
    int lane = tid & 31, wid = tid >> 5;
    int g = lane >> 2, t = lane & 3;
    int m0 = blockIdx.y * GBM;
    int n0 = blockIdx.x * GBN;
    int wm = (wid & 3) * 32;
    int wn = (wid >> 2) * 32;

    // staging: thread -> row r (0..127), chunk pair c0 / c0+4 of 16B chunks
    int r = tid >> 2, c0 = tid & 3;
    uint32_t smbase = smem_u32(sm);
    uint32_t adst = smbase + (uint32_t)(r * AP + c0 * 4) * 4;
    uint32_t bdst = adst + GBM * AP * 4;
    const __half* asrc = A + (size_t)(m0 + r) * KAP + c0 * 8;
    int nidx = n0 + r;
    uint32_t bok = (nidx < N) ? 16u : 0u;
    const __half* bsrc = W + (size_t)((nidx < N) ? nidx : 0) * 512 + c0 * 8;

    float acc[2][4][4];
#pragma unroll
    for (int mt = 0; mt < 2; mt++)
#pragma unroll
        for (int nt = 0; nt < 4; nt++)
#pragma unroll
            for (int i = 0; i < 4; i++) acc[mt][nt][i] = 0.f;

    // prologue: chunk 0 -> buffer 0
    {
        CP16(adst,      asrc);
        CP16(adst + 64, asrc + 32);
        CP16P(bdst,      bsrc,      bok);
        CP16P(bdst + 64, bsrc + 32, bok);
        CPCOMMIT();
    }

    for (int kt = 0; kt < KTC; kt++) {
        int buf = kt & 1;
        if (kt + 1 < KTC) {
            int koff = (kt + 1) * 64;
            uint32_t bo = (buf ^ 1) ? (uint32_t)GBUF * 4 : 0u;
            CP16(adst + bo,      asrc + koff);
            CP16(adst + bo + 64, asrc + koff + 32);
            CP16P(bdst + bo,      bsrc + koff,      bok);
            CP16P(bdst + bo + 64, bsrc + koff + 32, bok);
            CPCOMMIT();
            CPWAIT1();
        } else {
            CPWAIT0();
        }
        __syncthreads();

        const uint32_t* Ab = sm + (buf ? GBUF : 0);
        const uint32_t* Bb = Ab + GBM * AP;
#pragma unroll
        for (int ks = 0; ks < 4; ks++) {
            int kk = ks * 8 + 2 * t;
            uint32_t af[2][4], bf[4][2];
#pragma unroll
            for (int mt = 0; mt < 2; mt++) {
                const uint32_t* Ar = Ab + (wm + mt * 16 + g) * AP + kk;
                uint2 lo = *(const uint2*)Ar;
                uint2 hi = *(const uint2*)(Ar + 8 * AP);
                af[mt][0] = lo.x; af[mt][2] = lo.y;
                af[mt][1] = hi.x; af[mt][3] = hi.y;
            }
#pragma unroll
            for (int nt = 0; nt < 4; nt++) {
                uint2 bv = *(const uint2*)(Bb + (wn + nt * 8 + g) * AP + kk);
                bf[nt][0] = bv.x; bf[nt][1] = bv.y;
            }
#pragma unroll
            for (int mt = 0; mt < 2; mt++)
#pragma unroll
                for (int nt = 0; nt < 4; nt++)
                    MMA_F16(acc[mt][nt], af[mt], bf[nt]);
        }
        __syncthreads();
    }

#pragma unroll
    for (int mt = 0; mt < 2; mt++) {
        int row0 = m0 + wm + mt * 16 + g;
#pragma unroll
        for (int nt = 0; nt < 4; nt++) {
            int col = n0 + wn + nt * 8 + 2 * t;
            if (col < N) {
                float2 bv = *(const float2*)(bias + col);
                float2 o0, o1;
                o0.x = acc[mt][nt][0] + bv.x;
                o0.y = acc[mt][nt][1] + bv.y;
                o1.x = acc[mt][nt][2] + bv.x;
                o1.y = acc[mt][nt][3] + bv.y;
                if (mode == 2) {
                    int which = col / 500;
                    int rem   = col - which * 500;
                    int hh    = rem / 50;
                    int dd    = rem - hh * 50;
                    size_t p0 = (size_t)row0 * QKVP + which * 640 + hh * 64 + dd;
                    size_t p1 = (size_t)(row0 + 8) * QKVP + which * 640 + hh * 64 + dd;
                    __half* Ch = (__half*)Ct;
                    *(uint32_t*)(Ch + p0) = pack_h2(o0.x, o0.y);
                    *(uint32_t*)(Ch + p1) = pack_h2(o1.x, o1.y);
                } else {
                    size_t i0 = (size_t)row0 * N + col;
                    size_t i1 = (size_t)(row0 + 8) * N + col;
                    if (res) {
                        float2 r0v = *(const float2*)(res + i0);
                        float2 r1v = *(const float2*)(res + i1);
                        o0.x += r0v.x; o0.y += r0v.y;
                        o1.x += r1v.x; o1.y += r1v.y;
                    }
                    *(float2*)(C + i0) = o0;
                    *(float2*)(C + i1) = o1;
                    if (mode == 1) {
                        int pw = pidx(col >> 1);
                        uint32_t* Cw = (uint32_t*)Ct;
                        Cw[(size_t)row0 * KAPW + pw]       = pack_h2(o0.x, o0.y);
                        Cw[(size_t)(row0 + 8) * KAPW + pw] = pack_h2(o1.x, o1.y);
                    }
                }
            }
        }
    }
    // zero pad words of the fp16 copy: warps with wn==0 cover rows wm..wm+31
    if (mode == 1 && n0 == 0 && wid < 4 && lane < 16) {
        uint32_t* Cw = (uint32_t*)Ct;
#pragma unroll
        for (int rr = 0; rr < 2; rr++) {
            int row = m0 + wm + rr * 16 + (lane & 15);
            uint32_t* pz = Cw + (size_t)row * KAPW;
#pragma unroll
            for (int w = 0; w < 6; w++) pz[pidx(250 + w)] = 0u;
        }
    }
}

// =================== fp16 warp-mma flash attention (unchanged) ==============
#define AMQ 128
#define ANK 64
#define APW 36
#define ASM_BYTES (((AMQ + 2*ANK + 2*56 + AMQ) * APW) * 4 + 192)

__global__ __launch_bounds__(256, 3)
void attn_mma(const __half* __restrict__ qkvh,
              const unsigned char* __restrict__ mask,
              __half* __restrict__ outh) {
    extern __shared__ uint32_t dsm[];
    uint32_t* Qs  = dsm;                      // [128][36]
    uint32_t* Ks0 = Qs + AMQ * APW;           // [2][64][36]
    uint32_t* Vt0 = Ks0 + 2 * ANK * APW;      // [2][56][36]
    uint32_t* Ps  = Vt0 + 2 * 56 * APW;       // [128][36]
    unsigned char* msk = (unsigned char*)(Ps + AMQ * APW);  // [2][64]

    int tid  = threadIdx.x;
    int lane = tid & 31, wid = tid >> 5;
    int g = lane >> 2, t = lane & 3;
    int bh = blockIdx.y;
    int b  = bh / H, h = bh % H;
    int q0 = blockIdx.x * AMQ;
    const float scale = 0.14142135623730951f;

    for (int i = tid; i < 2 * 6 * 32; i += 256) {
        int bb = i / 192, rr = (i % 192) / 32, cc = i % 32;
        Vt0[bb * 56 * APW + (50 + rr) * APW + cc] = 0;
    }

    {
        int r = tid >> 1, e = tid & 1;
        const __half* src = qkvh + (size_t)(b * T + q0 + r) * QKVP + h * 64;
        uint32_t dst = smem_u32(Qs + r * APW);
#pragma unroll
        for (int c = e; c < 8; c += 2) CP16(dst + 16 * c, src + 8 * c);
        CPCOMMIT();
    }

    int jst = tid >> 2, qst = tid & 3;

    {
        const __half* ksrc = qkvh + (size_t)(b * T + jst) * QKVP + 640 + h * 64;
        uint32_t dst = smem_u32(Ks0 + jst * APW);
        CP16(dst + 16 * qst,       ksrc + 8 * qst);
        CP16(dst + 16 * (qst + 4), ksrc + 8 * (qst + 4));
        CPCOMMIT();
        const __half* vsrc = qkvh + (size_t)(b * T + jst) * QKVP + 1280 + h * 64;
#pragma unroll
        for (int p = qst; p < 25; p += 4) {
            uint32_t v = *(const uint32_t*)(vsrc + 2 * p);
            __half2 hv = *(__half2*)&v;
            ((__half*)(Vt0 + (2 * p) * APW))[jst]     = hv.x;
            ((__half*)(Vt0 + (2 * p + 1) * APW))[jst] = hv.y;
        }
        if (tid < ANK) msk[tid] = mask[b * T + tid];
    }

    int wq = wid * 16;
    const uint32_t* QA = Qs + (wq + g) * APW;
    const uint32_t* QB = Qs + (wq + g + 8) * APW;
    uint32_t* PsA = Ps + (wq + g) * APW;
    uint32_t* PsB = Ps + (wq + g + 8) * APW;

    float m0 = -1e30f, m1 = -1e30f, l0 = 0.f, l1 = 0.f;
    float oacc[7][4];
#pragma unroll
    for (int nt = 0; nt < 7; nt++)
#pragma unroll
        for (int i = 0; i < 4; i++) oacc[nt][i] = 0.f;

    for (int kt = 0; kt < T / ANK; kt++) {
        int buf = kt & 1;
        CPWAIT0();
        __syncthreads();

        if (kt + 1 < T / ANK) {
            int k1 = (kt + 1) * ANK;
            uint32_t* Ksn = Ks0 + (buf ^ 1) * ANK * APW;
            uint32_t* Vtn = Vt0 + (buf ^ 1) * 56 * APW;
            const __half* ksrc = qkvh + (size_t)(b * T + k1 + jst) * QKVP + 640 + h * 64;
            uint32_t dst = smem_u32(Ksn + jst * APW);
            CP16(dst + 16 * qst,       ksrc + 8 * qst);
            CP16(dst + 16 * (qst + 4), ksrc + 8 * (qst + 4));
            CPCOMMIT();
            const __half* vsrc = qkvh + (size_t)(b * T + k1 + jst) * QKVP + 1280 + h * 64;
#pragma unroll
            for (int p = qst; p < 25; p += 4) {
                uint32_t v = *(const uint32_t*)(vsrc + 2 * p);
                __half2 hv = *(__half2*)&v;
                ((__half*)(Vtn + (2 * p) * APW))[jst]     = hv.x;
                ((__half*)(Vtn + (2 * p + 1) * APW))[jst] = hv.y;
            }
            if (tid < ANK) msk[(buf ^ 1) * 64 + tid] = mask[b * T + k1 + tid];
        } else {
            CPCOMMIT();
        }

        const uint32_t* Ksb = Ks0 + buf * ANK * APW;
        const uint32_t* Vtb = Vt0 + buf * 56 * APW;
        const unsigned char* mskb = msk + buf * 64;

        float sacc[8][4];
#pragma unroll
        for (int nt = 0; nt < 8; nt++)
#pragma unroll
            for (int i = 0; i < 4; i++) sacc[nt][i] = 0.f;
#pragma unroll
        for (int ks = 0; ks < 4; ks++) {
            int kk = ks * 8;
            uint32_t af[4] = {QA[kk + t], QB[kk + t], QA[kk + t + 4], QB[kk + t + 4]};
#pragma unroll
            for (int nt = 0; nt < 8; nt++) {
                const uint32_t* Kr = Ksb + (nt * 8 + g) * APW + kk;
                uint32_t bf[2] = {Kr[t], Kr[t + 4]};
                MMA_F16(sacc[nt], af, bf);
            }
        }

        float mx0 = -1e30f, mx1 = -1e30f;
#pragma unroll
        for (int nt = 0; nt < 8; nt++) {
            sacc[nt][0] *= scale; sacc[nt][1] *= scale;
            sacc[nt][2] *= scale; sacc[nt][3] *= scale;
            int c = nt * 8 + 2 * t;
            if (mskb[c])     { sacc[nt][0] = -1e30f; sacc[nt][2] = -1e30f; }
            if (mskb[c + 1]) { sacc[nt][1] = -1e30f; sacc[nt][3] = -1e30f; }
            mx0 = fmaxf(mx0, fmaxf(sacc[nt][0], sacc[nt][1]));
            mx1 = fmaxf(mx1, fmaxf(sacc[nt][2], sacc[nt][3]));
        }
        mx0 = fmaxf(mx0, __shfl_xor_sync(0xffffffffu, mx0, 1));
        mx0 = fmaxf(mx0, __shfl_xor_sync(0xffffffffu, mx0, 2));
        mx1 = fmaxf(mx1, __shfl_xor_sync(0xffffffffu, mx1, 1));
        mx1 = fmaxf(mx1, __shfl_xor_sync(0xffffffffu, mx1, 2));
        float mn0 = fmaxf(m0, mx0), mn1 = fmaxf(m1, mx1);
        float c0 = __expf(m0 - mn0), c1 = __expf(m1 - mn1);
        float s0 = 0.f, s1 = 0.f;
#pragma unroll
        for (int nt = 0; nt < 8; nt++) {
            float p00 = __expf(sacc[nt][0] - mn0);
            float p01 = __expf(sacc[nt][1] - mn0);
            float p10 = __expf(sacc[nt][2] - mn1);
            float p11 = __expf(sacc[nt][3] - mn1);
            s0 += p00 + p01;
            s1 += p10 + p11;
            PsA[nt * 4 + t] = pack_h2(p00, p01);
            PsB[nt * 4 + t] = pack_h2(p10, p11);
        }
        s0 += __shfl_xor_sync(0xffffffffu, s0, 1);
        s0 += __shfl_xor_sync(0xffffffffu, s0, 2);
        s1 += __shfl_xor_sync(0xffffffffu, s1, 1);
        s1 += __shfl_xor_sync(0xffffffffu, s1, 2);
        l0 = l0 * c0 + s0; m0 = mn0;
        l1 = l1 * c1 + s1; m1 = mn1;
#pragma unroll
        for (int nt = 0; nt < 7; nt++) {
            oacc[nt][0] *= c0; oacc[nt][1] *= c0;
            oacc[nt][2] *= c1; oacc[nt][3] *= c1;
        }
        __syncwarp();

#pragma unroll
        for (int ks = 0; ks < 4; ks++) {
            int kk = ks * 8;
            uint32_t af[4] = {PsA[kk + t], PsB[kk + t], PsA[kk + t + 4], PsB[kk + t + 4]};
#pragma unroll
            for (int nt = 0; nt < 7; nt++) {
                const uint32_t* Vr = Vtb + (nt * 8 + g) * APW + kk;
                uint32_t bf[2] = {Vr[t], Vr[t + 4]};
                MMA_F16(oacc[nt], af, bf);
            }
        }
    }

    // epilogue: permuted fp16 output (consumer is out_proj GEMM A)
    float inv0 = 1.f / l0, inv1 = 1.f / l1;
    int r0 = q0 + wq + g;
    uint32_t* o0w = (uint32_t*)(outh + (size_t)(b * T + r0) * KAP);
    uint32_t* o1w = o0w + 8 * KAPW;
#pragma unroll
    for (int nt = 0; nt < 7; nt++) {
        int c = nt * 8 + 2 * t;
        if (c < HD) {
            int p = pidx(h * 25 + nt * 4 + t);
            o0w[p] = pack_h2(oacc[nt][0] * inv0, oacc[nt][1] * inv0);
            o1w[p] = pack_h2(oacc[nt][2] * inv1, oacc[nt][3] * inv1);
        }
    }
    if (h == 0 && lane < 16) {
        int row = q0 + wq + (lane & 15);
        uint32_t* pz = (uint32_t*)(outh + (size_t)(b * T + row) * KAP);
#pragma unroll
        for (int w = 0; w < 6; w++) pz[pidx(250 + w)] = 0u;
    }
}

// ---------------- launch ----------------------------------------------------
extern "C" void kernel_launch(void* const* d_in, const int* in_sizes, int n_in,
                              void* d_out, int out_size) {
    const int* ori            = (const int*)d_in[0];
    const float* x            = (const float*)d_in[1];
    const unsigned char* xm   = (const unsigned char*)d_in[2];
    const float *dwp[4], *dbp[4], *pwp[4], *pbp[4];
    for (int i = 0; i < 4; i++) {
        dwp[i] = (const float*)d_in[3 + 4 * i];
        dbp[i] = (const float*)d_in[4 + 4 * i];
        pwp[i] = (const float*)d_in[5 + 4 * i];
        pbp[i] = (const float*)d_in[6 + 4 * i];
    }
    const float* in_w  = (const float*)d_in[19];
    const float* in_b  = (const float*)d_in[20];
    const float* out_w = (const float*)d_in[21];
    const float* out_b = (const float*)d_in[22];
    const float* ffc_w = (const float*)d_in[23];
    const float* ffc_b = (const float*)d_in[24];
    float* outp = (float*)d_out;

    float *b0, *b1, *b2, *wtr, *pet;
    __half *bt, *b1t, *b2t, *wth, *qkvh;
    cudaGetSymbolAddress((void**)&b0,   g_b0);
    cudaGetSymbolAddress((void**)&b1,   g_b1);
    cudaGetSymbolAddress((void**)&b2,   g_b2);
    cudaGetSymbolAddress((void**)&bt,   g_bt);
    cudaGetSymbolAddress((void**)&b1t,  g_b1t);
    cudaGetSymbolAddress((void**)&b2t,  g_b2t);
    cudaGetSymbolAddress((void**)&qkvh, g_qkv);
    cudaGetSymbolAddress((void**)&wth,  g_wt);
    cudaGetSymbolAddress((void**)&wtr,  g_wtr);
    cudaGetSymbolAddress((void**)&pet,  g_pe);

    cudaFuncSetAttribute(attn_mma, cudaFuncAttributeMaxDynamicSharedMemorySize, ASM_BYTES);
    cudaFuncSetAttribute(gemm_pipe, cudaFuncAttributeMaxDynamicSharedMemorySize, GSM_BYTES);

    __half* wtp[4];
    for (int i = 0; i < 4; i++) wtp[i] = wth + i * PWS;
    __half* wt_in  = wth + 4 * PWS;
    __half* wt_out = wt_in + INS;
    __half* wt_ffc = wt_out + PWS;

    int ntot = NW + NTR + NPE + NQZ;
    prep_all<<<(ntot + 255) / 256, 256>>>(pwp[0], pwp[1], pwp[2], pwp[3],
                                          in_w, out_w, ffc_w,
                                          dwp[0], dwp[1], dwp[2], dwp[3],
                                          wth, wtr, pet, qkvh);

    int pblocks  = (BT * 125 + 255) / 256;
    int cblocks  = ((BT / 4) * 128 + 255) / 256;   // 2048
    dim3 gg5((D + GBN - 1) / GBN, BT / GBM);    // (4, 128)
    dim3 ggq((D3 + GBN - 1) / GBN, BT / GBM);   // (12, 128)
    dim3 gga(T / AMQ, B * H);                   // (4, 320)

    posemb_kernel<<<pblocks, 256>>>(ori, x, pet, b0);
    dwconv4_kernel<<<cblocks, 256>>>(b0, wtr + 0 * KW * D, dbp[0], bt);
    gemm_pipe<<<gg5, 512, GSM_BYTES>>>(bt, wtp[0], pbp[0], b0, b1, nullptr, D, 0);
    dwconv4_kernel<<<cblocks, 256>>>(b1, wtr + 1 * KW * D, dbp[1], bt);
    gemm_pipe<<<gg5, 512, GSM_BYTES>>>(bt, wtp[1], pbp[1], b1, b2, nullptr, D, 0);
    dwconv4_kernel<<<cblocks, 256>>>(b2, wtr + 2 * KW * D, dbp[2], bt);
    gemm_pipe<<<gg5, 512, GSM_BYTES>>>(bt, wtp[2], pbp[2], b2, b0, nullptr, D, 0);
    dwconv4_kernel<<<cblocks, 256>>>(b0, wtr + 3 * KW * D, dbp[3], bt);
    gemm_pipe<<<gg5, 512, GSM_BYTES>>>(bt, wtp[3], pbp[3], b0, b1, b1t, D, 1);
    gemm_pipe<<<ggq, 512, GSM_BYTES>>>(b1t, wt_in, in_b, nullptr, nullptr, qkvh, D3, 2);
    attn_mma<<<gga, 256, ASM_BYTES>>>(qkvh, xm, bt);
    gemm_pipe<<<gg5, 512, GSM_BYTES>>>(bt, wt_out, out_b, b1, b2, b2t, D, 1);
    gemm_pipe<<<gg5, 512, GSM_BYTES>>>(b2t, wt_ffc, ffc_b, b2, outp, nullptr, D, 0);
}

// round 17
// speedup vs baseline: 1.1119x; 1.1119x over previous
#include <cuda_runtime.h>
#include <cuda_fp16.h>
#include <cstdint>
#include <cstddef>

#define B 32
#define T 512
#define D 500
#define H 10
#define HD 50
#define D3 1500
#define BT (B*T)
#define BTD (BT*D)
#define KW 7
#define KAP 512      // padded activation K pitch (halves)
#define KAPW 256     // words per activation row
#define QKVP 1920    // padded qkv row pitch (halves): 3 * H * 64

// ---------------- scratch (static device arrays; no runtime allocation) ----
__device__ float  g_b0[BTD];
__device__ float  g_b1[BTD];
__device__ float  g_b2[BTD];
__device__ __half g_bt[(size_t)BT * KAP];
__device__ __half g_b1t[(size_t)BT * KAP];
__device__ __half g_b2t[(size_t)BT * KAP];
__device__ __half g_qkv[(size_t)BT * QKVP];
__device__ __half g_wt[2304000];             // padded fp16 weights (permuted)
__device__ float  g_wtr[4 * KW * D];         // transposed dwconv weights [K][D]
__device__ float  g_pe[T * D];               // positional embedding table

#define PWS 256000   // 500*512
#define INS 768000   // 1500*512
#define NW  (4 * PWS + INS + 2 * PWS)        // 2,304,000 weight halves
#define NTR (4 * KW * D)                     // 14,000 transposed dw weights
#define NPE (T * D)                          // 256,000 PE entries
#define NQZ (BT * 30)                        // 491,520 qkv pad zero jobs

// ---------------- helpers ---------------------------------------------------
__device__ __forceinline__ uint32_t smem_u32(const void* p) {
    uint32_t a;
    asm("{ .reg .u64 t; cvta.to.shared.u64 t, %1; cvt.u32.u64 %0, t; }" : "=r"(a) : "l"(p));
    return a;
}
__device__ __forceinline__ uint32_t pack_h2(float lo, float hi) {
    __half2 h = __floats2half2_rn(lo, hi);
    return *(uint32_t*)&h;
}
// fragment-pair permutation within each 8-word block: new[2k]=old k, new[2k+1]=old k+4
__device__ __forceinline__ int pidx(int w) {
    return (w & ~7) | ((w & 3) << 1) | ((w >> 2) & 1);
}

#define MMA_F16(c, a, b) \
    asm volatile("mma.sync.aligned.m16n8k16.row.col.f32.f16.f16.f32 " \
        "{%0,%1,%2,%3}, {%4,%5,%6,%7}, {%8,%9}, {%0,%1,%2,%3};" \
        : "+f"((c)[0]), "+f"((c)[1]), "+f"((c)[2]), "+f"((c)[3]) \
        : "r"((a)[0]), "r"((a)[1]), "r"((a)[2]), "r"((a)[3]), \
          "r"((b)[0]), "r"((b)[1]))

#define CP16(dst, src) \
    asm volatile("cp.async.ca.shared.global [%0], [%1], 16;" :: "r"(dst), "l"(src) : "memory")
#define CP16P(dst, src, p) \
    asm volatile("cp.async.ca.shared.global [%0], [%1], 16, %2;" :: "r"(dst), "l"(src), "r"(p) : "memory")
#define CPCOMMIT() asm volatile("cp.async.commit_group;" ::: "memory")
#define CPWAIT0()  asm volatile("cp.async.wait_group 0;" ::: "memory")
#define CPWAIT1()  asm volatile("cp.async.wait_group 1;" ::: "memory")

// -------- merged prep: weights fp16 pad-convert (PERMUTED) + dwconv
//          transpose + PE table + qkv pad zero -------------------------------
__global__ void prep_all(const float* __restrict__ p0, const float* __restrict__ p1,
                         const float* __restrict__ p2, const float* __restrict__ p3,
                         const float* __restrict__ p4, const float* __restrict__ p5,
                         const float* __restrict__ p6,
                         const float* __restrict__ dw0, const float* __restrict__ dw1,
                         const float* __restrict__ dw2, const float* __restrict__ dw3,
                         __half* __restrict__ wh, float* __restrict__ otr,
                         float* __restrict__ pe, __half* __restrict__ qkv) {
    int i = blockIdx.x * blockDim.x + threadIdx.x;
    if (i < NW) {
        const float* src;
        int idx;
        if      (i < PWS)          { src = p0; idx = i; }
        else if (i < 2 * PWS)      { src = p1; idx = i - PWS; }
        else if (i < 3 * PWS)      { src = p2; idx = i - 2 * PWS; }
        else if (i < 4 * PWS)      { src = p3; idx = i - 3 * PWS; }
        else if (i < 4 * PWS + INS){ src = p4; idx = i - 4 * PWS; }
        else if (i < 5 * PWS + INS){ src = p5; idx = i - 4 * PWS - INS; }
        else                       { src = p6; idx = i - 5 * PWS - INS; }
        int row = idx >> 9, col = idx & 511;
        float v = (col < 500) ? src[row * 500 + col] : 0.f;
        int newcol = (pidx(col >> 1) << 1) | (col & 1);
        wh[(i & ~511) | newcol] = __float2half(v);
        return;
    }
    int i2 = i - NW;
    if (i2 < NTR) {
        int arr = i2 / (KW * D);
        int rem = i2 - arr * (KW * D);
        int j = rem / D;
        int d = rem - j * D;
        const float* src = (arr == 0) ? dw0 : (arr == 1) ? dw1 : (arr == 2) ? dw2 : dw3;
        otr[arr * KW * D + j * D + d] = src[d * KW + j];
        return;
    }
    int i3 = i2 - NTR;
    if (i3 < NPE) {
        int t = i3 / D, d = i3 - t * D;
        float pos = (float)(t + 1);
        int   k   = (d < 250) ? d : (d - 250);
        float ang = pos * expf((float)k * -0.036989318763f);
        pe[i3] = (d < 250) ? sinf(ang) : cosf(ang);
        return;
    }
    int i4 = i3 - NPE;
    if (i4 < NQZ) {
        int row = i4 / 30, slot = i4 - row * 30;
        uint32_t* p = (uint32_t*)(qkv + (size_t)row * QKVP + slot * 64 + 50);
#pragma unroll
        for (int w = 0; w < 7; w++) p[w] = 0u;
    }
}

// ------- dwconv #1 fused with posemb: computes pe+x inline, writes b0 ------
__global__ void dwconv_pe_kernel(const int* __restrict__ ori,
                                 const float* __restrict__ x,
                                 const float* __restrict__ tab,
                                 const float* __restrict__ wT,   // [KW][D]
                                 const float* __restrict__ bias,
                                 float* __restrict__ b0,
                                 __half* __restrict__ y) {
    int idx = blockIdx.x * blockDim.x + threadIdx.x;
    if (idx >= (BT / 4) * 128) return;
    int d4  = idx & 127;
    int btq = idx >> 7;
    int b   = btq >> 7;          // T/4 = 128
    int t0  = (btq & 127) * 4;
    uint32_t* yw = (uint32_t*)(y + (size_t)(b * T + t0) * KAP);
    int p0 = pidx(d4 * 2), p1 = pidx(d4 * 2 + 1);
    if (d4 >= 125) {
#pragma unroll
        for (int r = 0; r < 4; r++) {
            uint32_t* row = yw + (size_t)r * KAPW;
            row[p0] = 0u; row[p1] = 0u;
        }
        return;
    }
    int d = d4 * 4;
    float4 bv = *(const float4*)(bias + d);
    float acc[4][4];
#pragma unroll
    for (int r = 0; r < 4; r++) {
        acc[r][0] = bv.x; acc[r][1] = bv.y; acc[r][2] = bv.z; acc[r][3] = bv.w;
    }
    float4 w4[KW];
#pragma unroll
    for (int j = 0; j < KW; j++) w4[j] = *(const float4*)(wT + j * D + d);

    const float* xb = x + (size_t)(b * T) * D + d;
    float* b0b = b0 + (size_t)(b * T) * D + d;
#pragma unroll
    for (int s = 0; s < 10; s++) {
        int tt = t0 + s - 3;
        if (tt >= 0 && tt < T) {
            float4 v = *(const float4*)(xb + (size_t)tt * D);
            if (ori[b * T + tt] != 0) {
                float4 pv = *(const float4*)(tab + tt * D + d);
                v.x += pv.x; v.y += pv.y; v.z += pv.z; v.w += pv.w;
            }
            if (s >= 3 && s <= 6)                 // owned rows t0..t0+3
                *(float4*)(b0b + (size_t)tt * D) = v;
#pragma unroll
            for (int r = 0; r < 4; r++) {
                int j = s - r;
                if (j >= 0 && j < KW) {
                    acc[r][0] = fmaf(w4[j].x, v.x, acc[r][0]);
                    acc[r][1] = fmaf(w4[j].y, v.y, acc[r][1]);
                    acc[r][2] = fmaf(w4[j].z, v.z, acc[r][2]);
                    acc[r][3] = fmaf(w4[j].w, v.w, acc[r][3]);
                }
            }
        }
    }
#pragma unroll
    for (int r = 0; r < 4; r++) {
        uint32_t* row = yw + (size_t)r * KAPW;
        row[p0] = pack_h2(acc[r][0], acc[r][1]);
        row[p1] = pack_h2(acc[r][2], acc[r][3]);
    }
}

// ------- depthwise conv1d: 4 t-outputs per thread, PERMUTED fp16 out -------
__global__ void dwconv4_kernel(const float* __restrict__ x,
                               const float* __restrict__ wT,   // [KW][D]
                               const float* __restrict__ bias,
                               __half* __restrict__ y) {
    int idx = blockIdx.x * blockDim.x + threadIdx.x;
    if (idx >= (BT / 4) * 128) return;
    int d4  = idx & 127;
    int btq = idx >> 7;
    int b   = btq >> 7;          // T/4 = 128
    int t0  = (btq & 127) * 4;
    uint32_t* yw = (uint32_t*)(y + (size_t)(b * T + t0) * KAP);
    int p0 = pidx(d4 * 2), p1 = pidx(d4 * 2 + 1);
    if (d4 >= 125) {
#pragma unroll
        for (int r = 0; r < 4; r++) {
            uint32_t* row = yw + (size_t)r * KAPW;
            row[p0] = 0u; row[p1] = 0u;
        }
        return;
    }
    int d = d4 * 4;
    float4 bv = *(const float4*)(bias + d);
    float acc[4][4];
#pragma unroll
    for (int r = 0; r < 4; r++) {
        acc[r][0] = bv.x; acc[r][1] = bv.y; acc[r][2] = bv.z; acc[r][3] = bv.w;
    }
    float4 w4[KW];
#pragma unroll
    for (int j = 0; j < KW; j++) w4[j] = *(const float4*)(wT + j * D + d);

    const float* xb = x + (size_t)(b * T) * D + d;
#pragma unroll
    for (int s = 0; s < 10; s++) {
        int tt = t0 + s - 3;
        if (tt >= 0 && tt < T) {
            float4 v = *(const float4*)(xb + (size_t)tt * D);
#pragma unroll
            for (int r = 0; r < 4; r++) {
                int j = s - r;
                if (j >= 0 && j < KW) {
                    acc[r][0] = fmaf(w4[j].x, v.x, acc[r][0]);
                    acc[r][1] = fmaf(w4[j].y, v.y, acc[r][1]);
                    acc[r][2] = fmaf(w4[j].z, v.z, acc[r][2]);
                    acc[r][3] = fmaf(w4[j].w, v.w, acc[r][3]);
                }
            }
        }
    }
#pragma unroll
    for (int r = 0; r < 4; r++) {
        uint32_t* row = yw + (size_t)r * KAPW;
        row[p0] = pack_h2(acc[r][0], acc[r][1]);
        row[p1] = pack_h2(acc[r][2], acc[r][3]);
    }
}

// =================== pipelined fp16 warp-mma GEMM (round-15 proven) =========
// 8 warps x (64x32); 2-stage cp.async; permuted LDS.64 fragments, pitch 40.
#define GBM 128
#define GBN 128
#define AP 40
#define GBUF ((GBM + GBN) * AP)
#define GSM_BYTES (2 * GBUF * 4)
#define KTC 8   // 512 / 64

__global__ __launch_bounds__(256, 2)
void gemm_pipe(const __half* __restrict__ A, const __half* __restrict__ W,
               const float* __restrict__ bias, const float* __restrict__ res,
               float* __restrict__ C, __half* __restrict__ Ct,
               int N, int mode) {
    extern __shared__ uint32_t sm[];

    int tid  = threadIdx.x;
    int lane = tid & 31, wid = tid >> 5;
    int g = lane >> 2, t = lane & 3;
    int m0 = blockIdx.y * GBM;
    int n0 = blockIdx.x * GBN;
    int wm = (wid & 1) * 64;
    int wn = (wid >> 1) * 32;

    int r0 = tid >> 3, kg = tid & 7;
    uint32_t smbase = smem_u32(sm);
    uint32_t adst[4], bdst[4];
    const __half* asrc[4];
    const __half* bsrc[4];
    uint32_t bok[4];
#pragma unroll
    for (int i = 0; i < 4; i++) {
        int r = r0 + i * 32;
        adst[i] = smbase + (uint32_t)(r * AP + kg * 4) * 4;
        bdst[i] = adst[i] + GBM * AP * 4;
        asrc[i] = A + (size_t)(m0 + r) * KAP + kg * 8;
        int n = n0 + r;
        bok[i] = (n < N) ? 16u : 0u;
        bsrc[i] = W + (size_t)((n < N) ? n : 0) * 512 + kg * 8;
    }

    float acc[4][4][4];
#pragma unroll
    for (int mt = 0; mt < 4; mt++)
#pragma unroll
        for (int nt = 0; nt < 4; nt++)
#pragma unroll
            for (int i = 0; i < 4; i++) acc[mt][nt][i] = 0.f;

    {
#pragma unroll
        for (int i = 0; i < 4; i++) {
            CP16(adst[i], asrc[i]);
            CP16P(bdst[i], bsrc[i], bok[i]);
        }
        CPCOMMIT();
    }

    for (int kt = 0; kt < KTC; kt++) {
        int buf = kt & 1;
        if (kt + 1 < KTC) {
            int koff = (kt + 1) * 64;
            uint32_t bo = (buf ^ 1) ? (uint32_t)GBUF * 4 : 0u;
#pragma unroll
            for (int i = 0; i < 4; i++) {
                CP16(adst[i] + bo, asrc[i] + koff);
                CP16P(bdst[i] + bo, bsrc[i] + koff, bok[i]);
            }
            CPCOMMIT();
            CPWAIT1();
        } else {
            CPWAIT0();
        }
        __syncthreads();

        const uint32_t* Ab = sm + (buf ? GBUF : 0);
        const uint32_t* Bb = Ab + GBM * AP;
#pragma unroll
        for (int ks = 0; ks < 4; ks++) {
            int kk = ks * 8 + 2 * t;
            uint32_t af[4][4], bf[4][2];
#pragma unroll
            for (int mt = 0; mt < 4; mt++) {
                const uint32_t* Ar = Ab + (wm + mt * 16 + g) * AP + kk;
                uint2 lo = *(const uint2*)Ar;
                uint2 hi = *(const uint2*)(Ar + 8 * AP);
                af[mt][0] = lo.x; af[mt][2] = lo.y;
                af[mt][1] = hi.x; af[mt][3] = hi.y;
            }
#pragma unroll
            for (int nt = 0; nt < 4; nt++) {
                uint2 bv = *(const uint2*)(Bb + (wn + nt * 8 + g) * AP + kk);
                bf[nt][0] = bv.x; bf[nt][1] = bv.y;
            }
#pragma unroll
            for (int mt = 0; mt < 4; mt++)
#pragma unroll
                for (int nt = 0; nt < 4; nt++)
                    MMA_F16(acc[mt][nt], af[mt], bf[nt]);
        }
        __syncthreads();
    }

#pragma unroll
    for (int mt = 0; mt < 4; mt++) {
        int row0 = m0 + wm + mt * 16 + g;
#pragma unroll
        for (int nt = 0; nt < 4; nt++) {
            int col = n0 + wn + nt * 8 + 2 * t;
            if (col < N) {
                float2 bv = *(const float2*)(bias + col);
                float2 o0, o1;
                o0.x = acc[mt][nt][0] + bv.x;
                o0.y = acc[mt][nt][1] + bv.y;
                o1.x = acc[mt][nt][2] + bv.x;
                o1.y = acc[mt][nt][3] + bv.y;
                if (mode == 2) {
                    int which = col / 500;
                    int rem   = col - which * 500;
                    int hh    = rem / 50;
                    int dd    = rem - hh * 50;
                    size_t p0 = (size_t)row0 * QKVP + which * 640 + hh * 64 + dd;
                    size_t p1 = (size_t)(row0 + 8) * QKVP + which * 640 + hh * 64 + dd;
                    __half* Ch = (__half*)Ct;
                    *(uint32_t*)(Ch + p0) = pack_h2(o0.x, o0.y);
                    *(uint32_t*)(Ch + p1) = pack_h2(o1.x, o1.y);
                } else {
                    size_t i0 = (size_t)row0 * N + col;
                    size_t i1 = (size_t)(row0 + 8) * N + col;
                    if (res) {
                        float2 r0v = *(const float2*)(res + i0);
                        float2 r1v = *(const float2*)(res + i1);
                        o0.x += r0v.x; o0.y += r0v.y;
                        o1.x += r1v.x; o1.y += r1v.y;
                    }
                    *(float2*)(C + i0) = o0;
                    *(float2*)(C + i1) = o1;
                    if (mode == 1) {
                        int pw = pidx(col >> 1);
                        uint32_t* Cw = (uint32_t*)Ct;
                        Cw[(size_t)row0 * KAPW + pw]       = pack_h2(o0.x, o0.y);
                        Cw[(size_t)(row0 + 8) * KAPW + pw] = pack_h2(o1.x, o1.y);
                    }
                }
            }
        }
    }
    if (mode == 1 && n0 == 0 && lane < 16) {
        int row = m0 + wm + (lane & 15);
        uint32_t* Cw = (uint32_t*)Ct;
#pragma unroll
        for (int rr = 0; rr < 4; rr++) {
            uint32_t* pz = Cw + (size_t)(row + rr * 16) * KAPW;
#pragma unroll
            for (int w = 0; w < 6; w++) pz[pidx(250 + w)] = 0u;
        }
    }
}

// =================== fp16 warp-mma flash attention (unchanged) ==============
#define AMQ 128
#define ANK 64
#define APW 36
#define ASM_BYTES (((AMQ + 2*ANK + 2*56 + AMQ) * APW) * 4 + 192)

__global__ __launch_bounds__(256, 3)
void attn_mma(const __half* __restrict__ qkvh,
              const unsigned char* __restrict__ mask,
              __half* __restrict__ outh) {
    extern __shared__ uint32_t dsm[];
    uint32_t* Qs  = dsm;                      // [128][36]
    uint32_t* Ks0 = Qs + AMQ * APW;           // [2][64][36]
    uint32_t* Vt0 = Ks0 + 2 * ANK * APW;      // [2][56][36]
    uint32_t* Ps  = Vt0 + 2 * 56 * APW;       // [128][36]
    unsigned char* msk = (unsigned char*)(Ps + AMQ * APW);  // [2][64]

    int tid  = threadIdx.x;
    int lane = tid & 31, wid = tid >> 5;
    int g = lane >> 2, t = lane & 3;
    int bh = blockIdx.y;
    int b  = bh / H, h = bh % H;
    int q0 = blockIdx.x * AMQ;
    const float scale = 0.14142135623730951f;

    for (int i = tid; i < 2 * 6 * 32; i += 256) {
        int bb = i / 192, rr = (i % 192) / 32, cc = i % 32;
        Vt0[bb * 56 * APW + (50 + rr) * APW + cc] = 0;
    }

    {
        int r = tid >> 1, e = tid & 1;
        const __half* src = qkvh + (size_t)(b * T + q0 + r) * QKVP + h * 64;
        uint32_t dst = smem_u32(Qs + r * APW);
#pragma unroll
        for (int c = e; c < 8; c += 2) CP16(dst + 16 * c, src + 8 * c);
        CPCOMMIT();
    }

    int jst = tid >> 2, qst = tid & 3;

    {
        const __half* ksrc = qkvh + (size_t)(b * T + jst) * QKVP + 640 + h * 64;
        uint32_t dst = smem_u32(Ks0 + jst * APW);
        CP16(dst + 16 * qst,       ksrc + 8 * qst);
        CP16(dst + 16 * (qst + 4), ksrc + 8 * (qst + 4));
        CPCOMMIT();
        const __half* vsrc = qkvh + (size_t)(b * T + jst) * QKVP + 1280 + h * 64;
#pragma unroll
        for (int p = qst; p < 25; p += 4) {
            uint32_t v = *(const uint32_t*)(vsrc + 2 * p);
            __half2 hv = *(__half2*)&v;
            ((__half*)(Vt0 + (2 * p) * APW))[jst]     = hv.x;
            ((__half*)(Vt0 + (2 * p + 1) * APW))[jst] = hv.y;
        }
        if (tid < ANK) msk[tid] = mask[b * T + tid];
    }

    int wq = wid * 16;
    const uint32_t* QA = Qs + (wq + g) * APW;
    const uint32_t* QB = Qs + (wq + g + 8) * APW;
    uint32_t* PsA = Ps + (wq + g) * APW;
    uint32_t* PsB = Ps + (wq + g + 8) * APW;

    float m0 = -1e30f, m1 = -1e30f, l0 = 0.f, l1 = 0.f;
    float oacc[7][4];
#pragma unroll
    for (int nt = 0; nt < 7; nt++)
#pragma unroll
        for (int i = 0; i < 4; i++) oacc[nt][i] = 0.f;

    for (int kt = 0; kt < T / ANK; kt++) {
        int buf = kt & 1;
        CPWAIT0();
        __syncthreads();

        if (kt + 1 < T / ANK) {
            int k1 = (kt + 1) * ANK;
            uint32_t* Ksn = Ks0 + (buf ^ 1) * ANK * APW;
            uint32_t* Vtn = Vt0 + (buf ^ 1) * 56 * APW;
            const __half* ksrc = qkvh + (size_t)(b * T + k1 + jst) * QKVP + 640 + h * 64;
            uint32_t dst = smem_u32(Ksn + jst * APW);
            CP16(dst + 16 * qst,       ksrc + 8 * qst);
            CP16(dst + 16 * (qst + 4), ksrc + 8 * (qst + 4));
            CPCOMMIT();
            const __half* vsrc = qkvh + (size_t)(b * T + k1 + jst) * QKVP + 1280 + h * 64;
#pragma unroll
            for (int p = qst; p < 25; p += 4) {
                uint32_t v = *(const uint32_t*)(vsrc + 2 * p);
                __half2 hv = *(__half2*)&v;
                ((__half*)(Vtn + (2 * p) * APW))[jst]     = hv.x;
                ((__half*)(Vtn + (2 * p + 1) * APW))[jst] = hv.y;
            }
            if (tid < ANK) msk[(buf ^ 1) * 64 + tid] = mask[b * T + k1 + tid];
        } else {
            CPCOMMIT();
        }

        const uint32_t* Ksb = Ks0 + buf * ANK * APW;
        const uint32_t* Vtb = Vt0 + buf * 56 * APW;
        const unsigned char* mskb = msk + buf * 64;

        float sacc[8][4];
#pragma unroll
        for (int nt = 0; nt < 8; nt++)
#pragma unroll
            for (int i = 0; i < 4; i++) sacc[nt][i] = 0.f;
#pragma unroll
        for (int ks = 0; ks < 4; ks++) {
            int kk = ks * 8;
            uint32_t af[4] = {QA[kk + t], QB[kk + t], QA[kk + t + 4], QB[kk + t + 4]};
#pragma unroll
            for (int nt = 0; nt < 8; nt++) {
                const uint32_t* Kr = Ksb + (nt * 8 + g) * APW + kk;
                uint32_t bf[2] = {Kr[t], Kr[t + 4]};
                MMA_F16(sacc[nt], af, bf);
            }
        }

        float mx0 = -1e30f, mx1 = -1e30f;
#pragma unroll
        for (int nt = 0; nt < 8; nt++) {
            sacc[nt][0] *= scale; sacc[nt][1] *= scale;
            sacc[nt][2] *= scale; sacc[nt][3] *= scale;
            int c = nt * 8 + 2 * t;
            if (mskb[c])     { sacc[nt][0] = -1e30f; sacc[nt][2] = -1e30f; }
            if (mskb[c + 1]) { sacc[nt][1] = -1e30f; sacc[nt][3] = -1e30f; }
            mx0 = fmaxf(mx0, fmaxf(sacc[nt][0], sacc[nt][1]));
            mx1 = fmaxf(mx1, fmaxf(sacc[nt][2], sacc[nt][3]));
        }
        mx0 = fmaxf(mx0, __shfl_xor_sync(0xffffffffu, mx0, 1));
        mx0 = fmaxf(mx0, __shfl_xor_sync(0xffffffffu, mx0, 2));
        mx1 = fmaxf(mx1, __shfl_xor_sync(0xffffffffu, mx1, 1));
        mx1 = fmaxf(mx1, __shfl_xor_sync(0xffffffffu, mx1, 2));
        float mn0 = fmaxf(m0, mx0), mn1 = fmaxf(m1, mx1);
        float c0 = __expf(m0 - mn0), c1 = __expf(m1 - mn1);
        float s0 = 0.f, s1 = 0.f;
#pragma unroll
        for (int nt = 0; nt < 8; nt++) {
            float p00 = __expf(sacc[nt][0] - mn0);
            float p01 = __expf(sacc[nt][1] - mn0);
            float p10 = __expf(sacc[nt][2] - mn1);
            float p11 = __expf(sacc[nt][3] - mn1);
            s0 += p00 + p01;
            s1 += p10 + p11;
            PsA[nt * 4 + t] = pack_h2(p00, p01);
            PsB[nt * 4 + t] = pack_h2(p10, p11);
        }
        s0 += __shfl_xor_sync(0xffffffffu, s0, 1);
        s0 += __shfl_xor_sync(0xffffffffu, s0, 2);
        s1 += __shfl_xor_sync(0xffffffffu, s1, 1);
        s1 += __shfl_xor_sync(0xffffffffu, s1, 2);
        l0 = l0 * c0 + s0; m0 = mn0;
        l1 = l1 * c1 + s1; m1 = mn1;
#pragma unroll
        for (int nt = 0; nt < 7; nt++) {
            oacc[nt][0] *= c0; oacc[nt][1] *= c0;
            oacc[nt][2] *= c1; oacc[nt][3] *= c1;
        }
        __syncwarp();

#pragma unroll
        for (int ks = 0; ks < 4; ks++) {
            int kk = ks * 8;
            uint32_t af[4] = {PsA[kk + t], PsB[kk + t], PsA[kk + t + 4], PsB[kk + t + 4]};
#pragma unroll
            for (int nt = 0; nt < 7; nt++) {
                const uint32_t* Vr = Vtb + (nt * 8 + g) * APW + kk;
                uint32_t bf[2] = {Vr[t], Vr[t + 4]};
                MMA_F16(oacc[nt], af, bf);
            }
        }
    }

    float inv0 = 1.f / l0, inv1 = 1.f / l1;
    int r0 = q0 + wq + g;
    uint32_t* o0w = (uint32_t*)(outh + (size_t)(b * T + r0) * KAP);
    uint32_t* o1w = o0w + 8 * KAPW;
#pragma unroll
    for (int nt = 0; nt < 7; nt++) {
        int c = nt * 8 + 2 * t;
        if (c < HD) {
            int p = pidx(h * 25 + nt * 4 + t);
            o0w[p] = pack_h2(oacc[nt][0] * inv0, oacc[nt][1] * inv0);
            o1w[p] = pack_h2(oacc[nt][2] * inv1, oacc[nt][3] * inv1);
        }
    }
    if (h == 0 && lane < 16) {
        int row = q0 + wq + (lane & 15);
        uint32_t* pz = (uint32_t*)(outh + (size_t)(b * T + row) * KAP);
#pragma unroll
        for (int w = 0; w < 6; w++) pz[pidx(250 + w)] = 0u;
    }
}

// ---------------- launch ----------------------------------------------------
extern "C" void kernel_launch(void* const* d_in, const int* in_sizes, int n_in,
                              void* d_out, int out_size) {
    const int* ori            = (const int*)d_in[0];
    const float* x            = (const float*)d_in[1];
    const unsigned char* xm   = (const unsigned char*)d_in[2];
    const float *dwp[4], *dbp[4], *pwp[4], *pbp[4];
    for (int i = 0; i < 4; i++) {
        dwp[i] = (const float*)d_in[3 + 4 * i];
        dbp[i] = (const float*)d_in[4 + 4 * i];
        pwp[i] = (const float*)d_in[5 + 4 * i];
        pbp[i] = (const float*)d_in[6 + 4 * i];
    }
    const float* in_w  = (const float*)d_in[19];
    const float* in_b  = (const float*)d_in[20];
    const float* out_w = (const float*)d_in[21];
    const float* out_b = (const float*)d_in[22];
    const float* ffc_w = (const float*)d_in[23];
    const float* ffc_b = (const float*)d_in[24];
    float* outp = (float*)d_out;

    float *b0, *b1, *b2, *wtr, *pet;
    __half *bt, *b1t, *b2t, *wth, *qkvh;
    cudaGetSymbolAddress((void**)&b0,   g_b0);
    cudaGetSymbolAddress((void**)&b1,   g_b1);
    cudaGetSymbolAddress((void**)&b2,   g_b2);
    cudaGetSymbolAddress((void**)&bt,   g_bt);
    cudaGetSymbolAddress((void**)&b1t,  g_b1t);
    cudaGetSymbolAddress((void**)&b2t,  g_b2t);
    cudaGetSymbolAddress((void**)&qkvh, g_qkv);
    cudaGetSymbolAddress((void**)&wth,  g_wt);
    cudaGetSymbolAddress((void**)&wtr,  g_wtr);
    cudaGetSymbolAddress((void**)&pet,  g_pe);

    cudaFuncSetAttribute(attn_mma, cudaFuncAttributeMaxDynamicSharedMemorySize, ASM_BYTES);
    cudaFuncSetAttribute(gemm_pipe, cudaFuncAttributeMaxDynamicSharedMemorySize, GSM_BYTES);

    __half* wtp[4];
    for (int i = 0; i < 4; i++) wtp[i] = wth + i * PWS;
    __half* wt_in  = wth + 4 * PWS;
    __half* wt_out = wt_in + INS;
    __half* wt_ffc = wt_out + PWS;

    int ntot = NW + NTR + NPE + NQZ;
    prep_all<<<(ntot + 255) / 256, 256>>>(pwp[0], pwp[1], pwp[2], pwp[3],
                                          in_w, out_w, ffc_w,
                                          dwp[0], dwp[1], dwp[2], dwp[3],
                                          wth, wtr, pet, qkvh);

    int cblocks  = ((BT / 4) * 128 + 255) / 256;   // 2048
    dim3 gg5((D + GBN - 1) / GBN, BT / GBM);    // (4, 128)
    dim3 ggq((D3 + GBN - 1) / GBN, BT / GBM);   // (12, 128)
    dim3 gga(T / AMQ, B * H);                   // (4, 320)

    dwconv_pe_kernel<<<cblocks, 256>>>(ori, x, pet, wtr + 0 * KW * D, dbp[0], b0, bt);
    gemm_pipe<<<gg5, 256, GSM_BYTES>>>(bt, wtp[0], pbp[0], b0, b1, nullptr, D, 0);
    dwconv4_kernel<<<cblocks, 256>>>(b1, wtr + 1 * KW * D, dbp[1], bt);
    gemm_pipe<<<gg5, 256, GSM_BYTES>>>(bt, wtp[1], pbp[1], b1, b2, nullptr, D, 0);
    dwconv4_kernel<<<cblocks, 256>>>(b2, wtr + 2 * KW * D, dbp[2], bt);
    gemm_pipe<<<gg5, 256, GSM_BYTES>>>(bt, wtp[2], pbp[2], b2, b0, nullptr, D, 0);
    dwconv4_kernel<<<cblocks, 256>>>(b0, wtr + 3 * KW * D, dbp[3], bt);
    gemm_pipe<<<gg5, 256, GSM_BYTES>>>(bt, wtp[3], pbp[3], b0, b1, b1t, D, 1);
    gemm_pipe<<<ggq, 256, GSM_BYTES>>>(b1t, wt_in, in_b, nullptr, nullptr, qkvh, D3, 2);
    attn_mma<<<gga, 256, ASM_BYTES>>>(qkvh, xm, bt);
    gemm_pipe<<<gg5, 256, GSM_BYTES>>>(bt, wt_out, out_b, b1, b2, b2t, D, 1);
    gemm_pipe<<<gg5, 256, GSM_BYTES>>>(b2t, wt_ffc, ffc_b, b2, outp, nullptr, D, 0);
}